// round 11
// baseline (speedup 1.0000x reference)
#include <cuda_runtime.h>
#include <cstdint>

// PWLU channelwise activation, scalar bounds ±2.3, n_points=7 (n_regions=6).
// x: [B=64, C=256, H=56, W=56] fp32; points: [C,7]; left_diffs/right_diffs: [C].
// out = fp[c][r] + (xn - r) * df[c][r],  xn=(x-sim_left)/region_len, r=clip int.
//
// R10: R4 policy (default loads, evict-first .cs stores) + 256-bit global
// accesses (Blackwell LDG.E.256/STG.256 via ld/st.global.v8.f32). 1024B
// contiguous per warp-access -> longer HBM bursts per direction, fewer
// read<->write turnarounds. One CTA per (b,c) slice: 392 float8, 128 thr x3
// front-batched + tail(8).

#define BOUND_F 2.3f
#define N_POINTS 7
#define N_REGIONS 6
#define C_DIM 256
#define HW 3136            // 56*56 floats per slice
#define HW8 392            // float8 per slice
#define THREADS 128

struct F8 { float v[8]; };

__device__ __forceinline__ F8 ldg256(const float* p) {
    F8 r;
    asm volatile("ld.global.v8.f32 {%0,%1,%2,%3,%4,%5,%6,%7}, [%8];"
                 : "=f"(r.v[0]), "=f"(r.v[1]), "=f"(r.v[2]), "=f"(r.v[3]),
                   "=f"(r.v[4]), "=f"(r.v[5]), "=f"(r.v[6]), "=f"(r.v[7])
                 : "l"(p));
    return r;
}

__device__ __forceinline__ void stg256_cs(float* p, const F8& r) {
    asm volatile("st.global.cs.v8.f32 [%0], {%1,%2,%3,%4,%5,%6,%7,%8};"
                 :: "l"(p),
                    "f"(r.v[0]), "f"(r.v[1]), "f"(r.v[2]), "f"(r.v[3]),
                    "f"(r.v[4]), "f"(r.v[5]), "f"(r.v[6]), "f"(r.v[7])
                 : "memory");
}

__global__ __launch_bounds__(THREADS)
void pwlu_kernel(const float* __restrict__ x,
                 const float* __restrict__ points,
                 const float* __restrict__ left_diffs,
                 const float* __restrict__ right_diffs,
                 float* __restrict__ out) {
    const int bc = blockIdx.x;          // b*C + c
    const int c  = bc & (C_DIM - 1);
    const int tid = threadIdx.x;

    // Per-channel (false_point, diff) table in shared memory.
    __shared__ float2 tab[8];           // tab[r] = {fp[r], df[r]}
    if (tid < 8) {
        const float* p = points + c * N_POINTS;
        float fp, df;
        if (tid == 0)            { df = left_diffs[c];  fp = p[0] - df; }
        else if (tid == N_POINTS){ df = right_diffs[c]; fp = p[N_POINTS - 1]; }
        else                     { df = p[tid] - p[tid - 1]; fp = p[tid - 1]; }
        tab[tid] = make_float2(fp, df);
    }
    __syncthreads();

    const float region_len = (2.0f * BOUND_F) / (float)N_REGIONS;
    const float inv_rl     = (float)N_REGIONS / (2.0f * BOUND_F);
    const float sim_left   = -BOUND_F - region_len;
    const float clip_hi    = (float)(N_REGIONS + 1) * 1.001f;   // 7.007

    const float* __restrict__ xin = x + (size_t)bc * HW;
    float* __restrict__ o         = out + (size_t)bc * HW;

    // 392 float8 per slice, 128 threads: tid, +128, +256 always valid;
    // +384 valid for tid < 8. Front-batch all loads before dependent work.
    const bool tail = (tid < HW8 - 384);    // tid < 8
    F8 v0 = ldg256(xin + (size_t)tid * 8);
    F8 v1 = ldg256(xin + (size_t)(tid + 128) * 8);
    F8 v2 = ldg256(xin + (size_t)(tid + 256) * 8);
    F8 v3;
    if (tail) v3 = ldg256(xin + (size_t)(tid + 384) * 8);

    auto pwlu1 = [&](float xv) -> float {
        float xn = (xv - sim_left) * inv_rl;
        float rf = fminf(fmaxf(xn, 0.0f), clip_hi);
        int   r  = __float2int_rz(rf);
        float d  = xn - (float)r;
        float2 t = tab[r];
        return fmaf(d, t.y, t.x);
    };
    auto pwlu8 = [&](const F8& v) -> F8 {
        F8 r;
        #pragma unroll
        for (int i = 0; i < 8; i++) r.v[i] = pwlu1(v.v[i]);
        return r;
    };

    stg256_cs(o + (size_t)tid * 8,         pwlu8(v0));
    stg256_cs(o + (size_t)(tid + 128) * 8, pwlu8(v1));
    stg256_cs(o + (size_t)(tid + 256) * 8, pwlu8(v2));
    if (tail) stg256_cs(o + (size_t)(tid + 384) * 8, pwlu8(v3));
}

extern "C" void kernel_launch(void* const* d_in, const int* in_sizes, int n_in,
                              void* d_out, int out_size) {
    const float* x  = (const float*)d_in[0];
    const float* p  = (const float*)d_in[1];
    const float* ld = (const float*)d_in[2];
    const float* rd = (const float*)d_in[3];
    float* out = (float*)d_out;

    const int B = 64;
    const int n_blocks = B * C_DIM;     // 16384
    pwlu_kernel<<<n_blocks, THREADS>>>(x, p, ld, rd, out);
}